// round 14
// baseline (speedup 1.0000x reference)
#include <cuda_runtime.h>
#include <cstdint>

#define CDIM 256
#define NDIM 512
#define TM   32
#define NTH  256
#define KITER 15
#define ATS  36                    // a_t padded row stride (floats)
#define ATFLOATS (NDIM * ATS)      // 18432 floats
#define CES  34                    // ceff padded col stride (floats, even for u64 align)

typedef unsigned long long u64;

// Device-global scratch (allocation-free), value-duplicated weight layouts.
__device__ float g_Wsd[NDIM * 2 * NDIM];     // [k=512][1024]  dup symmetrized W
__device__ float g_WinTd[CDIM * 2 * NDIM];   // [k=256][1024]  dup W_in^T
__device__ float g_WoutTd[NDIM * 2 * CDIM];  // [k=512][512]   dup W_out^T

// ---------- packed f32x2 helpers ----------
__device__ __forceinline__ u64 pack2(float lo, float hi) {
    u64 r; asm("mov.b64 %0,{%1,%2};" : "=l"(r) : "f"(lo), "f"(hi)); return r;
}
__device__ __forceinline__ float2 unpack2(u64 v) {
    float2 f; asm("mov.b64 {%0,%1},%2;" : "=f"(f.x), "=f"(f.y) : "l"(v)); return f;
}
__device__ __forceinline__ u64 fma2(u64 a, u64 b, u64 c) {
    u64 d; asm("fma.rn.f32x2 %0,%1,%2,%3;" : "=l"(d) : "l"(a), "l"(b), "l"(c)); return d;
}
__device__ __forceinline__ u64 add2(u64 a, u64 b) {
    u64 d; asm("add.rn.f32x2 %0,%1,%2;" : "=l"(d) : "l"(a), "l"(b)); return d;
}
__device__ __forceinline__ float tanh_fast(float v) {
    float r; asm("tanh.approx.f32 %0,%1;" : "=f"(r) : "f"(v)); return r;
}
__device__ __forceinline__ float tanh_accurate(float v) {
    float e = __expf(2.0f * v);
    return 1.0f - 2.0f / (e + 1.0f);
}

// ---------- per-warp GEMM streaming W straight from L2 via LDG ----------
// acc[p][c]: row-pair p (rows 2p,2p+1) packed f32x2; c = lane-local column.
// gw: this lane's slice in the dup weight matrix (row stride ROWF floats).
// NC==2: one LDG.128 per k yields (w0,w0),(w1,w1).  NC==1: one LDG.64.
template <int K, int NC, int ROWF>
__device__ __forceinline__ void stream_gemm_ldg(const float* __restrict__ gw,
                                                const float* __restrict__ a_t,
                                                u64 (&acc)[16][NC]) {
    constexpr int PF = 4;                 // prefetch depth (registers)
    u64 wbuf[PF][NC];
#pragma unroll
    for (int i = 0; i < PF; i++) {
        if (NC == 2) {
            ulonglong2 t = *(const ulonglong2*)(gw + (long)i * ROWF);
            wbuf[i][0] = t.x; wbuf[i][NC - 1] = t.y;
        } else {
            wbuf[i][0] = *(const u64*)(gw + (long)i * ROWF);
        }
    }
#pragma unroll 1
    for (int kb = 0; kb < K; kb += PF) {
#pragma unroll
        for (int kk = 0; kk < PF; kk++) {
            const int k = kb + kk;
            u64 w0 = wbuf[kk][0];
            u64 w1 = wbuf[kk][NC - 1];
            // prefetch k+PF (clamped in-bounds; garbage value never used)
            long knext = (k + PF < K) ? (k + PF) : k;
            if (NC == 2) {
                ulonglong2 t = *(const ulonglong2*)(gw + knext * ROWF);
                wbuf[kk][0] = t.x; wbuf[kk][NC - 1] = t.y;
            } else {
                wbuf[kk][0] = *(const u64*)(gw + knext * ROWF);
            }
            // a column vector (32 rows = 16 f32x2), broadcast LDS.128
            const ulonglong2* ap = (const ulonglong2*)(a_t + k * ATS);
            u64 a8[16];
#pragma unroll
            for (int q = 0; q < 8; q++) { ulonglong2 t = ap[q]; a8[2*q] = t.x; a8[2*q+1] = t.y; }
            if (NC == 2) {
#pragma unroll
                for (int p = 0; p < 16; p++) {
                    acc[p][0]      = fma2(a8[p], w0, acc[p][0]);
                    acc[p][NC - 1] = fma2(a8[p], w1, acc[p][NC - 1]);
                }
            } else {
#pragma unroll
                for (int p = 0; p < 16; p++) acc[p][0] = fma2(a8[p], w0, acc[p][0]);
            }
        }
    }
}

// ---------- prep: build duplicated weight layouts ----------
__global__ void prep_kernel(const float* __restrict__ W_in,
                            const float* __restrict__ W,
                            const float* __restrict__ W_out) {
    int i = blockIdx.x * blockDim.x + threadIdx.x;
    if (i < NDIM * NDIM) {
        int k = i >> 9, n = i & 511;
        float v = 0.5f * (W[i] + W[n * NDIM + k]);
        g_Wsd[k * 1024 + 2 * n] = v; g_Wsd[k * 1024 + 2 * n + 1] = v;
    }
    if (i < CDIM * NDIM) {
        int k = i >> 9, n = i & 511;
        float v = W_in[n * CDIM + k];
        g_WinTd[k * 1024 + 2 * n] = v; g_WinTd[k * 1024 + 2 * n + 1] = v;
    }
    if (i < NDIM * CDIM) {
        int k = i >> 8, j = i & 255;
        float v = W_out[j * NDIM + k];
        g_WoutTd[k * 512 + 2 * j] = v; g_WoutTd[k * 512 + 2 * j + 1] = v;
    }
}

// ---------- fused attractor kernel ----------
__global__ void __launch_bounds__(NTH, 1)
attractor_kernel(const float* __restrict__ x, const float* __restrict__ b_in,
                 const float* __restrict__ bvec, const float* __restrict__ b_out,
                 float* __restrict__ y) {
    extern __shared__ float smem[];
    float* a_t     = smem;                  // [512 k][32 rows], stride ATS
    float* ceff_sm = smem + ATFLOATS;       // [512 cols][32 rows], stride CES

    const int tid  = threadIdx.x;
    const int wid  = tid >> 5;
    const int lane = tid & 31;
    const long row0 = (long)blockIdx.x * TM;
    const int c0 = 64 * wid + 2 * lane;     // this lane's 2 columns

    // ===== stage x transposed into a_t (tid = channel) =====
#pragma unroll 4
    for (int r = 0; r < TM; r++)
        a_t[tid * ATS + r] = x[(row0 + r) * CDIM + tid];
    __syncthreads();

    u64 acc[16][2];

    // ===== Phase A: c = x @ W_in^T (K=256); fold biases; stash ceff in smem =====
#pragma unroll
    for (int p = 0; p < 16; p++) { acc[p][0] = 0ull; acc[p][1] = 0ull; }
    stream_gemm_ldg<CDIM, 2, 1024>(g_WinTd + wid * 128 + lane * 4, a_t, acc);
    {
        u64 bb0 = pack2(b_in[c0] + bvec[c0], b_in[c0] + bvec[c0]);
        u64 bb1 = pack2(b_in[c0+1] + bvec[c0+1], b_in[c0+1] + bvec[c0+1]);
#pragma unroll
        for (int p = 0; p < 16; p++) {
            acc[p][0] = add2(acc[p][0], bb0);
            acc[p][1] = add2(acc[p][1], bb1);
            *(u64*)(ceff_sm + c0 * CES + 2 * p)       = acc[p][0];
            *(u64*)(ceff_sm + (c0 + 1) * CES + 2 * p) = acc[p][1];
        }
    }

    // ===== iteration 1: a1 = tanh(ceff)  (a0 = 0, GEMM skipped) =====
    __syncthreads();    // all warps done reading x from a_t
#pragma unroll
    for (int c = 0; c < 2; c++) {
        float v[32];
#pragma unroll
        for (int p = 0; p < 16; p++) {
            float2 f = unpack2(acc[p][c]);
            v[2*p] = tanh_fast(f.x); v[2*p+1] = tanh_fast(f.y);
        }
        float* dst = a_t + (c0 + c) * ATS;
#pragma unroll
        for (int q = 0; q < 8; q++)
            *(float4*)(dst + 4*q) = make_float4(v[4*q], v[4*q+1], v[4*q+2], v[4*q+3]);
    }
    __syncthreads();

    // ===== iterations 2..15: a = tanh(a @ Ws + ceff) =====
#pragma unroll 1
    for (int t = 0; t < KITER - 1; t++) {
        const bool last = (t == KITER - 2);
#pragma unroll
        for (int p = 0; p < 16; p++) {
            acc[p][0] = *(const u64*)(ceff_sm + c0 * CES + 2 * p);
            acc[p][1] = *(const u64*)(ceff_sm + (c0 + 1) * CES + 2 * p);
        }

        stream_gemm_ldg<NDIM, 2, 1024>(g_Wsd + wid * 128 + lane * 4, a_t, acc);

        __syncthreads();    // all warps done reading a_t
#pragma unroll
        for (int c = 0; c < 2; c++) {
            float v[32];
#pragma unroll
            for (int p = 0; p < 16; p++) {
                float2 f = unpack2(acc[p][c]);
                if (last) { v[2*p] = tanh_accurate(f.x); v[2*p+1] = tanh_accurate(f.y); }
                else      { v[2*p] = tanh_fast(f.x);     v[2*p+1] = tanh_fast(f.y); }
            }
            float* dst = a_t + (c0 + c) * ATS;
#pragma unroll
            for (int q = 0; q < 8; q++)
                *(float4*)(dst + 4*q) = make_float4(v[4*q], v[4*q+1], v[4*q+2], v[4*q+3]);
        }
        __syncthreads();
    }

    // ===== Phase C: y = a @ W_out^T + b_out  (1 output col per lane) =====
    {
        const int col = 32 * wid + lane;
        u64 oacc[16][1];
        float bo = b_out[col];
#pragma unroll
        for (int p = 0; p < 16; p++) oacc[p][0] = pack2(bo, bo);

        stream_gemm_ldg<NDIM, 1, 512>(g_WoutTd + wid * 64 + lane * 2, a_t, oacc);

        __syncthreads();    // all warps done reading a_t; reuse as y staging
#pragma unroll
        for (int p = 0; p < 16; p++)
            *(u64*)(a_t + col * ATS + 2 * p) = oacc[p][0];
        __syncthreads();

#pragma unroll 4
        for (int r = 0; r < TM; r++)
            y[(row0 + r) * CDIM + tid] = a_t[tid * ATS + r];
    }
}

extern "C" void kernel_launch(void* const* d_in, const int* in_sizes, int n_in,
                              void* d_out, int out_size) {
    const float* x     = (const float*)d_in[0];
    const float* W_in  = (const float*)d_in[1];
    const float* b_in  = (const float*)d_in[2];
    const float* W     = (const float*)d_in[3];
    const float* bvec  = (const float*)d_in[4];
    const float* W_out = (const float*)d_in[5];
    const float* b_out = (const float*)d_in[6];
    float* y = (float*)d_out;

    const int rows = in_sizes[0] / CDIM;            // 65536
    const int nblk = rows / TM;                     // 2048
    const int smem_bytes = (ATFLOATS + NDIM * CES) * 4;  // 73728 + 69632 = 143360

    cudaFuncSetAttribute(attractor_kernel,
                         cudaFuncAttributeMaxDynamicSharedMemorySize, smem_bytes);

    prep_kernel<<<1024, 256>>>(W_in, W, W_out);
    attractor_kernel<<<nblk, NTH, smem_bytes>>>(x, b_in, bvec, b_out, y);
}

// round 16
// speedup vs baseline: 5.8405x; 5.8405x over previous
#include <cuda_runtime.h>
#include <cuda_fp16.h>
#include <cstdint>

#define NTH 256
#define AS  520            // A smem stride in halves (1040B, 260 words ≡ 4 mod 32: ldmatrix conflict-free)
#define BS  72             // B chunk stride in halves (144B, 36 words ≡ 4 mod 32)

// ---- device-global scratch (allocation-free) ----
__device__ __half g_WsI[512 * 512];    // [n][k] fp16 symmetrized W
__device__ __half g_WinH[512 * 256];   // [n][k] hi(W_in)
__device__ __half g_WinL[512 * 256];   // [n][k] lo(W_in)
__device__ __half g_WoutH[256 * 512];  // [j][n] hi(W_out)
__device__ __half g_WoutL[256 * 512];  // [j][n] lo(W_out)
__device__ float  g_ceff[33554432];    // 65536 x 512 fp32 drive term

// ---------- helpers ----------
__device__ __forceinline__ uint32_t smem_u32(const void* p) {
    uint32_t a; asm("{ .reg .u64 t; cvta.to.shared.u64 t, %1; cvt.u32.u64 %0, t; }" : "=r"(a) : "l"(p));
    return a;
}
__device__ __forceinline__ float tanh_fast(float v) {
    float r; asm("tanh.approx.f32 %0,%1;" : "=f"(r) : "f"(v)); return r;
}
__device__ __forceinline__ float tanh_acc(float v) {
    float e = __expf(2.0f * v); return 1.0f - 2.0f / (e + 1.0f);
}
__device__ __forceinline__ void cpa16(uint32_t d, const void* s) {
    asm volatile("cp.async.cg.shared.global [%0], [%1], 16;" :: "r"(d), "l"(s));
}
__device__ __forceinline__ void cpcommit() { asm volatile("cp.async.commit_group;" ::); }
__device__ __forceinline__ void ldm4(uint32_t* r, uint32_t a) {
    asm volatile("ldmatrix.sync.aligned.m8n8.x4.shared.b16 {%0,%1,%2,%3}, [%4];"
                 : "=r"(r[0]), "=r"(r[1]), "=r"(r[2]), "=r"(r[3]) : "r"(a));
}
__device__ __forceinline__ void hmma(float* c, const uint32_t* a, uint32_t b0, uint32_t b1) {
    asm volatile("mma.sync.aligned.m16n8k16.row.col.f32.f16.f16.f32 "
                 "{%0,%1,%2,%3},{%4,%5,%6,%7},{%8,%9},{%0,%1,%2,%3};"
                 : "+f"(c[0]), "+f"(c[1]), "+f"(c[2]), "+f"(c[3])
                 : "r"(a[0]), "r"(a[1]), "r"(a[2]), "r"(a[3]), "r"(b0), "r"(b1));
}

// ---------- cp.async chunk copy: ROWS rows x 64 halves from [row][k] image ----------
template <int ROWS>
__device__ __forceinline__ void copy_chunk(uint32_t sB, const __half* g, int ktotB, int kcoffB, int tid) {
#pragma unroll
    for (int i = 0; i < ROWS * 8 / NTH; i++) {
        int t = i * NTH + tid;
        int row = t >> 3, off = (t & 7) * 16;
        cpa16(sB + row * (BS * 2) + off, (const char*)g + (size_t)row * ktotB + kcoffB + off);
    }
}

// ---------- MMA pass: acc += A[:, abase:abase+K] @ B^T, B streamed in 64-k chunks ----------
template <int NT, int ROWS>
__device__ __forceinline__ void mma_pass(const __half* gB, int ktotB, int nch,
                                         int abase, int abase2, int cb,
                                         uint32_t sA, uint32_t sB0, uint32_t sB1,
                                         uint32_t aLane, uint32_t bLane, int tid,
                                         float (&acc)[4][NT][4]) {
    copy_chunk<ROWS>(sB0, gB, ktotB, 0, tid); cpcommit();
#pragma unroll 1
    for (int kc = 0; kc < nch; kc++) {
        uint32_t sBc = (kc & 1) ? sB1 : sB0;
        if (kc + 1 < nch) {
            copy_chunk<ROWS>((kc & 1) ? sB0 : sB1, gB, ktotB, (kc + 1) * 128, tid); cpcommit();
            asm volatile("cp.async.wait_group 1;" ::);
        } else {
            asm volatile("cp.async.wait_group 0;" ::);
        }
        __syncthreads();
#pragma unroll
        for (int ks = 0; ks < 4; ks++) {
            const int k = kc * 64 + ks * 16;
            uint32_t b[NT / 2][4];
#pragma unroll
            for (int g = 0; g < NT / 2; g++)
                ldm4(b[g], sBc + bLane + (uint32_t)(cb + g * 16) * (BS * 2) + ks * 32);
            uint32_t a[4][4];
#pragma unroll
            for (int rt = 0; rt < 4; rt++)
                ldm4(a[rt], sA + aLane + (uint32_t)(rt * 16) * (AS * 2) + (uint32_t)(abase + k) * 2);
#pragma unroll
            for (int rt = 0; rt < 4; rt++)
#pragma unroll
                for (int nt = 0; nt < NT; nt++)
                    hmma(acc[rt][nt], a[rt], b[nt >> 1][(nt & 1) * 2], b[nt >> 1][(nt & 1) * 2 + 1]);
            if (abase2 >= 0) {   // second A operand (xl) into the same accumulators
#pragma unroll
                for (int rt = 0; rt < 4; rt++)
                    ldm4(a[rt], sA + aLane + (uint32_t)(rt * 16) * (AS * 2) + (uint32_t)(abase2 + k) * 2);
#pragma unroll
                for (int rt = 0; rt < 4; rt++)
#pragma unroll
                    for (int nt = 0; nt < NT; nt++)
                        hmma(acc[rt][nt], a[rt], b[nt >> 1][(nt & 1) * 2], b[nt >> 1][(nt & 1) * 2 + 1]);
            }
        }
        __syncthreads();
    }
}

// ---------- prep: fp16 weight images (hi/lo where accuracy matters) ----------
__global__ void prep_h(const float* __restrict__ W_in, const float* __restrict__ W,
                       const float* __restrict__ W_out) {
    int i = blockIdx.x * blockDim.x + threadIdx.x;
    if (i < 262144) {                     // Ws [n][k]
        int n = i >> 9, k = i & 511;
        g_WsI[i] = __float2half_rn(0.5f * (W[n * 512 + k] + W[k * 512 + n]));
    }
    if (i < 131072) {                     // W_in hi/lo (512x256 row-major already [n][k])
        float v = W_in[i];
        __half h = __float2half_rn(v);
        g_WinH[i] = h;
        g_WinL[i] = __float2half_rn(v - __half2float(h));
    }
    if (i < 131072) {                     // W_out hi/lo (256x512 row-major already [j][n])
        float v = W_out[i];
        __half h = __float2half_rn(v);
        g_WoutH[i] = h;
        g_WoutL[i] = __float2half_rn(v - __half2float(h));
    }
}

// ---------- main fused kernel ----------
__global__ void __launch_bounds__(NTH, 1)
attractor_hmma(const float* __restrict__ x, const float* __restrict__ b_in,
               const float* __restrict__ bvec, const float* __restrict__ b_out,
               float* __restrict__ y) {
    extern __shared__ __align__(16) char smem[];
    uint32_t s0 = smem_u32(smem);
    uint32_t sA = s0, sB0 = s0 + 66560, sB1 = s0 + 66560 + 73728;
    __half* Ah = (__half*)smem;

    const int tid = threadIdx.x, lane = tid & 31, wid = tid >> 5;
    const long row0 = (long)blockIdx.x * 64;
    float* ceff = g_ceff + (size_t)blockIdx.x * (64 * 512);

    const uint32_t aLane = (uint32_t)(lane & 15) * (AS * 2) + ((lane >> 4) & 1) * 16;
    const uint32_t bLane = (uint32_t)((lane & 7) + ((lane >> 4) & 1) * 8) * (BS * 2) + ((lane >> 3) & 1) * 16;
    const int qr = lane >> 2, qc = (lane & 3) * 2;
    const int cb = wid * 64;

    // ===== stage x: hi halves -> A cols 0..255, lo halves -> A cols 256..511 =====
#pragma unroll 1
    for (int i = 0; i < 16; i++) {
        int t = i * NTH + tid;
        int r = t >> 6, q = (t & 63) * 4;
        float4 v = *(const float4*)(x + (row0 + r) * 256 + q);
        __half hx = __float2half_rn(v.x), hy = __float2half_rn(v.y);
        __half hz = __float2half_rn(v.z), hw = __float2half_rn(v.w);
        *(__half2*)(Ah + r * AS + q)     = __halves2half2(hx, hy);
        *(__half2*)(Ah + r * AS + q + 2) = __halves2half2(hz, hw);
        __half lx = __float2half_rn(v.x - __half2float(hx));
        __half ly = __float2half_rn(v.y - __half2float(hy));
        __half lz = __float2half_rn(v.z - __half2float(hz));
        __half lw = __float2half_rn(v.w - __half2float(hw));
        *(__half2*)(Ah + r * AS + 256 + q)     = __halves2half2(lx, ly);
        *(__half2*)(Ah + r * AS + 256 + q + 2) = __halves2half2(lz, lw);
    }
    __syncthreads();

    float acc[4][8][4];

    // ===== Phase A: c = xh@WinH^T + xl@WinH^T + xh@WinL^T  (fp32-accurate drive) =====
#pragma unroll
    for (int rt = 0; rt < 4; rt++)
#pragma unroll
        for (int nt = 0; nt < 8; nt++)
#pragma unroll
            for (int i = 0; i < 4; i++) acc[rt][nt][i] = 0.0f;
    mma_pass<8, 512>(g_WinH, 512, 4, 0, 256, cb, sA, sB0, sB1, aLane, bLane, tid, acc);
    mma_pass<8, 512>(g_WinL, 512, 4, 0, -1,  cb, sA, sB0, sB1, aLane, bLane, tid, acc);

    // epilogue A: ceff = c + b_in + b (fp32 -> global), a1 = tanh(ceff) -> A
#pragma unroll
    for (int rt = 0; rt < 4; rt++)
#pragma unroll
        for (int nt = 0; nt < 8; nt++) {
            int c0 = cb + nt * 8 + qc, r0 = rt * 16 + qr;
            float2 bi = *(const float2*)(b_in + c0);
            float2 bv = *(const float2*)(bvec + c0);
            float z0 = acc[rt][nt][0] + bi.x + bv.x, z1 = acc[rt][nt][1] + bi.y + bv.y;
            float z2 = acc[rt][nt][2] + bi.x + bv.x, z3 = acc[rt][nt][3] + bi.y + bv.y;
            *(float2*)(ceff + r0 * 512 + c0)       = make_float2(z0, z1);
            *(float2*)(ceff + (r0 + 8) * 512 + c0) = make_float2(z2, z3);
            *(__half2*)(Ah + r0 * AS + c0)       = __floats2half2_rn(tanh_fast(z0), tanh_fast(z1));
            *(__half2*)(Ah + (r0 + 8) * AS + c0) = __floats2half2_rn(tanh_fast(z2), tanh_fast(z3));
        }
    __syncthreads();

    // ===== iterations 2..15: a = tanh(a @ Ws^T + ceff) =====
#pragma unroll 1
    for (int t = 0; t < 14; t++) {
        const bool last = (t == 13);
#pragma unroll
        for (int rt = 0; rt < 4; rt++)
#pragma unroll
            for (int nt = 0; nt < 8; nt++)
#pragma unroll
                for (int i = 0; i < 4; i++) acc[rt][nt][i] = 0.0f;

        mma_pass<8, 512>(g_WsI, 1024, 8, 0, -1, cb, sA, sB0, sB1, aLane, bLane, tid, acc);

#pragma unroll
        for (int rt = 0; rt < 4; rt++)
#pragma unroll
            for (int nt = 0; nt < 8; nt++) {
                int c0 = cb + nt * 8 + qc, r0 = rt * 16 + qr;
                float2 e0 = *(const float2*)(ceff + r0 * 512 + c0);
                float2 e1 = *(const float2*)(ceff + (r0 + 8) * 512 + c0);
                float z0 = acc[rt][nt][0] + e0.x, z1 = acc[rt][nt][1] + e0.y;
                float z2 = acc[rt][nt][2] + e1.x, z3 = acc[rt][nt][3] + e1.y;
                float a0, a1, a2, a3;
                if (last) { a0 = tanh_acc(z0); a1 = tanh_acc(z1); a2 = tanh_acc(z2); a3 = tanh_acc(z3); }
                else      { a0 = tanh_fast(z0); a1 = tanh_fast(z1); a2 = tanh_fast(z2); a3 = tanh_fast(z3); }
                *(__half2*)(Ah + r0 * AS + c0)       = __floats2half2_rn(a0, a1);
                *(__half2*)(Ah + (r0 + 8) * AS + c0) = __floats2half2_rn(a2, a3);
            }
        __syncthreads();
    }

    // ===== Phase C: y = a @ WoutH^T + a @ WoutL^T + b_out =====
    {
        const int cb2 = wid * 32;
        float accC[4][4][4];
#pragma unroll
        for (int rt = 0; rt < 4; rt++)
#pragma unroll
            for (int nt = 0; nt < 4; nt++)
#pragma unroll
                for (int i = 0; i < 4; i++) accC[rt][nt][i] = 0.0f;

        mma_pass<4, 256>(g_WoutH, 1024, 8, 0, -1, cb2, sA, sB0, sB1, aLane, bLane, tid, accC);
        mma_pass<4, 256>(g_WoutL, 1024, 8, 0, -1, cb2, sA, sB0, sB1, aLane, bLane, tid, accC);

#pragma unroll
        for (int rt = 0; rt < 4; rt++)
#pragma unroll
            for (int nt = 0; nt < 4; nt++) {
                int c0 = cb2 + nt * 8 + qc, r0 = rt * 16 + qr;
                float2 bo = *(const float2*)(b_out + c0);
                *(float2*)(y + (row0 + r0) * 256 + c0) =
                    make_float2(accC[rt][nt][0] + bo.x, accC[rt][nt][1] + bo.y);
                *(float2*)(y + (row0 + r0 + 8) * 256 + c0) =
                    make_float2(accC[rt][nt][2] + bo.x, accC[rt][nt][3] + bo.y);
            }
    }
}

extern "C" void kernel_launch(void* const* d_in, const int* in_sizes, int n_in,
                              void* d_out, int out_size) {
    const float* x     = (const float*)d_in[0];
    const float* W_in  = (const float*)d_in[1];
    const float* b_in  = (const float*)d_in[2];
    const float* W     = (const float*)d_in[3];
    const float* bvec  = (const float*)d_in[4];
    const float* W_out = (const float*)d_in[5];
    const float* b_out = (const float*)d_in[6];
    float* y = (float*)d_out;

    const int rows = in_sizes[0] / 256;          // 65536
    const int nblk = rows / 64;                  // 1024
    const int smem_bytes = 66560 + 2 * 73728;    // A + 2 B buffers = 214016

    cudaFuncSetAttribute(attractor_hmma, cudaFuncAttributeMaxDynamicSharedMemorySize, smem_bytes);

    prep_h<<<512, 512>>>(W_in, W, W_out);
    attractor_hmma<<<nblk, NTH, smem_bytes>>>(x, b_in, bvec, b_out, y);
}

// round 17
// speedup vs baseline: 7.0563x; 1.2082x over previous
#include <cuda_runtime.h>
#include <cuda_fp16.h>
#include <cstdint>

#define NTH 256
#define AS  520            // A smem stride in halves (1040B): ldmatrix conflict-free
#define RSTRIDE 80         // ring row stride bytes (64B data + 16B pad): conflict-free

// ---- device-global scratch (allocation-free) ----
__device__ __half g_WsI[512 * 512];    // [n][k] fp16 symmetrized W
__device__ __half g_WinH[512 * 256];   // [n][k] hi(W_in)
__device__ __half g_WinL[512 * 256];   // [n][k] lo(W_in)
__device__ __half g_WoutH[256 * 512];  // [j][n] hi(W_out)
__device__ __half g_WoutL[256 * 512];  // [j][n] lo(W_out)
__device__ float  g_ceff[33554432];    // 65536 x 512 fp32 drive term

// ---------- helpers ----------
__device__ __forceinline__ uint32_t smem_u32(const void* p) {
    uint32_t a; asm("{ .reg .u64 t; cvta.to.shared.u64 t, %1; cvt.u32.u64 %0, t; }" : "=r"(a) : "l"(p));
    return a;
}
__device__ __forceinline__ float tanh_fast(float v) {
    float r; asm("tanh.approx.f32 %0,%1;" : "=f"(r) : "f"(v)); return r;
}
__device__ __forceinline__ float tanh_acc(float v) {
    float e = __expf(2.0f * v); return 1.0f - 2.0f / (e + 1.0f);
}
__device__ __forceinline__ void cpa16(uint32_t d, const void* s) {
    asm volatile("cp.async.cg.shared.global [%0], [%1], 16;" :: "r"(d), "l"(s));
}
__device__ __forceinline__ void cpcommit() { asm volatile("cp.async.commit_group;" ::); }
__device__ __forceinline__ void ldm4(uint32_t* r, uint32_t a) {
    asm volatile("ldmatrix.sync.aligned.m8n8.x4.shared.b16 {%0,%1,%2,%3}, [%4];"
                 : "=r"(r[0]), "=r"(r[1]), "=r"(r[2]), "=r"(r[3]) : "r"(a));
}
__device__ __forceinline__ void hmma(float* c, const uint32_t* a, uint32_t b0, uint32_t b1) {
    asm volatile("mma.sync.aligned.m16n8k16.row.col.f32.f16.f16.f32 "
                 "{%0,%1,%2,%3},{%4,%5,%6,%7},{%8,%9},{%0,%1,%2,%3};"
                 : "+f"(c[0]), "+f"(c[1]), "+f"(c[2]), "+f"(c[3])
                 : "r"(a[0]), "r"(a[1]), "r"(a[2]), "r"(a[3]), "r"(b0), "r"(b1));
}

// ---------- per-warp GEMM pass over a private cp.async ring ----------
// Warp owns 2*GT*8 output columns; consumes only its own RPW B-rows.
// gBw: this warp's B slice base ([row][k] halves, row stride rowHalves).
// Ring: 3 slots of RPW x 32k chunks, per-warp private -> NO block syncs.
template <int GT, int RPW>
__device__ __forceinline__ void pw_pass(const __half* gBw, int rowHalves, int nch,
                                        int abase, int abase2,
                                        uint32_t sA, uint32_t ring,
                                        uint32_t aLane, uint32_t bLane, int lane,
                                        float (&acc)[4][2 * GT][4]) {
    const int CH = RPW * RSTRIDE;
    auto issue = [&](int kc) {
        uint32_t dst = ring + (kc % 3) * CH;
        const char* src = (const char*)gBw + kc * 64;     // kc*32 halves
#pragma unroll
        for (int i = 0; i < RPW / 8; i++) {
            int idx = i * 32 + lane;
            int r = idx >> 2, u = idx & 3;
            cpa16(dst + r * RSTRIDE + u * 16, src + (size_t)r * (rowHalves * 2) + u * 16);
        }
        cpcommit();
    };
    issue(0); issue(1);
#pragma unroll 1
    for (int kc = 0; kc < nch; kc++) {
        if (kc + 2 < nch) issue(kc + 2); else cpcommit();   // uniform group count
        asm volatile("cp.async.wait_group 2;" ::);
        __syncwarp();
        uint32_t sB = ring + (kc % 3) * CH;
#pragma unroll
        for (int ks = 0; ks < 2; ks++) {
            const int k = kc * 32 + ks * 16;
            uint32_t b[GT][4];
#pragma unroll
            for (int g = 0; g < GT; g++)
                ldm4(b[g], sB + bLane + (uint32_t)(g * 16) * RSTRIDE + ks * 32);
            uint32_t a[4][4];
#pragma unroll
            for (int rt = 0; rt < 4; rt++)
                ldm4(a[rt], sA + aLane + (uint32_t)(rt * 16) * (AS * 2) + (uint32_t)(abase + k) * 2);
#pragma unroll
            for (int rt = 0; rt < 4; rt++)
#pragma unroll
                for (int nt = 0; nt < 2 * GT; nt++)
                    hmma(acc[rt][nt], a[rt], b[nt >> 1][(nt & 1) * 2], b[nt >> 1][(nt & 1) * 2 + 1]);
            if (abase2 >= 0) {    // second A operand (xl) into same accumulators
#pragma unroll
                for (int rt = 0; rt < 4; rt++)
                    ldm4(a[rt], sA + aLane + (uint32_t)(rt * 16) * (AS * 2) + (uint32_t)(abase2 + k) * 2);
#pragma unroll
                for (int rt = 0; rt < 4; rt++)
#pragma unroll
                    for (int nt = 0; nt < 2 * GT; nt++)
                        hmma(acc[rt][nt], a[rt], b[nt >> 1][(nt & 1) * 2], b[nt >> 1][(nt & 1) * 2 + 1]);
            }
        }
    }
}

// ---------- prep: fp16 weight images (hi/lo where accuracy matters) ----------
__global__ void prep_h(const float* __restrict__ W_in, const float* __restrict__ W,
                       const float* __restrict__ W_out) {
    int i = blockIdx.x * blockDim.x + threadIdx.x;
    if (i < 262144) {                     // Ws [n][k]
        int n = i >> 9, k = i & 511;
        g_WsI[i] = __float2half_rn(0.5f * (W[n * 512 + k] + W[k * 512 + n]));
    }
    if (i < 131072) {                     // W_in hi/lo ([n][k] row-major already)
        float v = W_in[i];
        __half h = __float2half_rn(v);
        g_WinH[i] = h;
        g_WinL[i] = __float2half_rn(v - __half2float(h));
    }
    if (i < 131072) {                     // W_out hi/lo ([j][n] row-major already)
        float v = W_out[i];
        __half h = __float2half_rn(v);
        g_WoutH[i] = h;
        g_WoutL[i] = __float2half_rn(v - __half2float(h));
    }
}

// ---------- main fused kernel ----------
__global__ void __launch_bounds__(NTH, 1)
attractor_hmma(const float* __restrict__ x, const float* __restrict__ b_in,
               const float* __restrict__ bvec, const float* __restrict__ b_out,
               float* __restrict__ y) {
    extern __shared__ __align__(16) char smem[];
    uint32_t s0 = smem_u32(smem);
    uint32_t sA = s0;
    __half* Ah = (__half*)smem;

    const int tid = threadIdx.x, lane = tid & 31, wid = tid >> 5;
    const uint32_t ring = s0 + 66560 + (uint32_t)wid * (3 * 64 * RSTRIDE);  // 15360/warp
    const long row0 = (long)blockIdx.x * 64;
    float* ceff = g_ceff + (size_t)blockIdx.x * (64 * 512);

    const uint32_t aLane = (uint32_t)(lane & 15) * (AS * 2) + ((lane >> 4) & 1) * 16;
    const uint32_t bLane = (uint32_t)((lane & 7) + ((lane >> 4) & 1) * 8) * RSTRIDE + ((lane >> 3) & 1) * 16;
    const int qr = lane >> 2, qc = (lane & 3) * 2;
    const int cb = wid * 64;

    // ===== stage x: hi halves -> A cols 0..255, lo halves -> A cols 256..511 =====
#pragma unroll 1
    for (int i = 0; i < 16; i++) {
        int t = i * NTH + tid;
        int r = t >> 6, q = (t & 63) * 4;
        float4 v = *(const float4*)(x + (row0 + r) * 256 + q);
        __half hx = __float2half_rn(v.x), hy = __float2half_rn(v.y);
        __half hz = __float2half_rn(v.z), hw = __float2half_rn(v.w);
        *(__half2*)(Ah + r * AS + q)     = __halves2half2(hx, hy);
        *(__half2*)(Ah + r * AS + q + 2) = __halves2half2(hz, hw);
        __half lx = __float2half_rn(v.x - __half2float(hx));
        __half ly = __float2half_rn(v.y - __half2float(hy));
        __half lz = __float2half_rn(v.z - __half2float(hz));
        __half lw = __float2half_rn(v.w - __half2float(hw));
        *(__half2*)(Ah + r * AS + 256 + q)     = __halves2half2(lx, ly);
        *(__half2*)(Ah + r * AS + 256 + q + 2) = __halves2half2(lz, lw);
    }
    __syncthreads();

    float acc[4][8][4];

    // ===== Phase A: c = xh@WinH^T + xl@WinH^T + xh@WinL^T =====
#pragma unroll
    for (int rt = 0; rt < 4; rt++)
#pragma unroll
        for (int nt = 0; nt < 8; nt++)
#pragma unroll
            for (int i = 0; i < 4; i++) acc[rt][nt][i] = 0.0f;
    pw_pass<4, 64>(g_WinH + (size_t)cb * 256, 256, 8, 0, 256, sA, ring, aLane, bLane, lane, acc);
    pw_pass<4, 64>(g_WinL + (size_t)cb * 256, 256, 8, 0, -1,  sA, ring, aLane, bLane, lane, acc);

    __syncthreads();    // all warps done reading x from A
#pragma unroll
    for (int rt = 0; rt < 4; rt++)
#pragma unroll
        for (int nt = 0; nt < 8; nt++) {
            int c0 = cb + nt * 8 + qc, r0 = rt * 16 + qr;
            float2 bi = *(const float2*)(b_in + c0);
            float2 bv = *(const float2*)(bvec + c0);
            float z0 = acc[rt][nt][0] + bi.x + bv.x, z1 = acc[rt][nt][1] + bi.y + bv.y;
            float z2 = acc[rt][nt][2] + bi.x + bv.x, z3 = acc[rt][nt][3] + bi.y + bv.y;
            *(float2*)(ceff + r0 * 512 + c0)       = make_float2(z0, z1);
            *(float2*)(ceff + (r0 + 8) * 512 + c0) = make_float2(z2, z3);
            *(__half2*)(Ah + r0 * AS + c0)       = __floats2half2_rn(tanh_fast(z0), tanh_fast(z1));
            *(__half2*)(Ah + (r0 + 8) * AS + c0) = __floats2half2_rn(tanh_fast(z2), tanh_fast(z3));
        }
    __syncthreads();

    // ===== iterations 2..15: a = tanh(a @ Ws^T + ceff) =====
#pragma unroll 1
    for (int t = 0; t < 14; t++) {
        const bool last = (t == 13);
#pragma unroll
        for (int rt = 0; rt < 4; rt++)
#pragma unroll
            for (int nt = 0; nt < 8; nt++)
#pragma unroll
                for (int i = 0; i < 4; i++) acc[rt][nt][i] = 0.0f;

        pw_pass<4, 64>(g_WsI + (size_t)cb * 512, 512, 16, 0, -1, sA, ring, aLane, bLane, lane, acc);

        __syncthreads();    // all warps done reading A
#pragma unroll
        for (int rt = 0; rt < 4; rt++)
#pragma unroll
            for (int nt = 0; nt < 8; nt++) {
                int c0 = cb + nt * 8 + qc, r0 = rt * 16 + qr;
                float2 e0 = *(const float2*)(ceff + r0 * 512 + c0);
                float2 e1 = *(const float2*)(ceff + (r0 + 8) * 512 + c0);
                float z0 = acc[rt][nt][0] + e0.x, z1 = acc[rt][nt][1] + e0.y;
                float z2 = acc[rt][nt][2] + e1.x, z3 = acc[rt][nt][3] + e1.y;
                float a0, a1, a2, a3;
                if (last) { a0 = tanh_acc(z0); a1 = tanh_acc(z1); a2 = tanh_acc(z2); a3 = tanh_acc(z3); }
                else      { a0 = tanh_fast(z0); a1 = tanh_fast(z1); a2 = tanh_fast(z2); a3 = tanh_fast(z3); }
                *(__half2*)(Ah + r0 * AS + c0)       = __floats2half2_rn(a0, a1);
                *(__half2*)(Ah + (r0 + 8) * AS + c0) = __floats2half2_rn(a2, a3);
            }
        __syncthreads();
    }

    // ===== Phase C: y = a @ WoutH^T + a @ WoutL^T + b_out =====
    {
        const int cb2 = wid * 32;
        float accC[4][4][4];
#pragma unroll
        for (int rt = 0; rt < 4; rt++)
#pragma unroll
            for (int nt = 0; nt < 4; nt++)
#pragma unroll
                for (int i = 0; i < 4; i++) accC[rt][nt][i] = 0.0f;

        pw_pass<2, 32>(g_WoutH + (size_t)cb2 * 512, 512, 16, 0, -1, sA, ring, aLane, bLane, lane, accC);
        pw_pass<2, 32>(g_WoutL + (size_t)cb2 * 512, 512, 16, 0, -1, sA, ring, aLane, bLane, lane, accC);

#pragma unroll
        for (int rt = 0; rt < 4; rt++)
#pragma unroll
            for (int nt = 0; nt < 4; nt++) {
                int c0 = cb2 + nt * 8 + qc, r0 = rt * 16 + qr;
                float2 bo = *(const float2*)(b_out + c0);
                *(float2*)(y + (row0 + r0) * 256 + c0) =
                    make_float2(accC[rt][nt][0] + bo.x, accC[rt][nt][1] + bo.y);
                *(float2*)(y + (row0 + r0 + 8) * 256 + c0) =
                    make_float2(accC[rt][nt][2] + bo.x, accC[rt][nt][3] + bo.y);
            }
    }
}

extern "C" void kernel_launch(void* const* d_in, const int* in_sizes, int n_in,
                              void* d_out, int out_size) {
    const float* x     = (const float*)d_in[0];
    const float* W_in  = (const float*)d_in[1];
    const float* b_in  = (const float*)d_in[2];
    const float* W     = (const float*)d_in[3];
    const float* bvec  = (const float*)d_in[4];
    const float* W_out = (const float*)d_in[5];
    const float* b_out = (const float*)d_in[6];
    float* y = (float*)d_out;

    const int rows = in_sizes[0] / 256;              // 65536
    const int nblk = rows / 64;                      // 1024
    const int smem_bytes = 66560 + 8 * (3 * 64 * RSTRIDE);   // A + 8 warp rings = 189440

    cudaFuncSetAttribute(attractor_hmma, cudaFuncAttributeMaxDynamicSharedMemorySize, smem_bytes);

    prep_h<<<512, 512>>>(W_in, W, W_out);
    attractor_hmma<<<nblk, NTH, smem_bytes>>>(x, b_in, bvec, b_out, y);
}